// round 2
// baseline (speedup 1.0000x reference)
#include <cuda_runtime.h>

#define NN 20000
#define NE 400000
#define NB 4
#define HID 256
#define OD 128

// Scratch (no allocations allowed): Y|Z concatenated per node row (512 floats), and S accumulator.
__device__ __align__(16) float g_YZ[NN * 512];
__device__ float g_S[NB * HID];
__device__ int g_is_i64; // 1 if edge_index is int64, 0 if int32 (written every launch)

typedef unsigned long long u64;

__device__ __forceinline__ u64 pk2(float lo, float hi) {
    u64 r;
    asm("mov.b64 %0, {%1, %2};" : "=l"(r) : "r"(__float_as_uint(lo)), "r"(__float_as_uint(hi)));
    return r;
}
__device__ __forceinline__ void upk2(u64 p, float &lo, float &hi) {
    unsigned a, b;
    asm("mov.b64 {%0, %1}, %2;" : "=r"(a), "=r"(b) : "l"(p));
    lo = __uint_as_float(a); hi = __uint_as_float(b);
}
__device__ __forceinline__ u64 fma2(u64 a, u64 b, u64 c) {
    u64 d;
    asm("fma.rn.f32x2 %0, %1, %2, %3;" : "=l"(d) : "l"(a), "l"(b), "l"(c));
    return d;
}
__device__ __forceinline__ u64 add2(u64 a, u64 b) {
    u64 d;
    asm("add.rn.f32x2 %0, %1, %2;" : "=l"(d) : "l"(a), "l"(b));
    return d;
}

// ---------------------------------------------------------------------------
// Kernel 0: detect edge_index dtype. If the buffer really holds int64 node ids
// (0 <= v < NN), the high 32 bits of every entry are 0. If it holds int32 ids,
// the "high word" is the next edge's id, nonzero w.p. 1 - 1/20000 per entry.
// Probe 64 entries -> misdetection probability ~0.
// ---------------------------------------------------------------------------
__global__ void detect_dtype(const void* __restrict__ eraw) {
    const long long* p = (const long long*)eraw;
    int lane = threadIdx.x;
    long long v0 = p[lane];
    long long v1 = p[64 + lane];
    bool ok = (v0 >= 0 && v0 < NN) && (v1 >= 0 && v1 < NN);
    unsigned m = __ballot_sync(0xffffffffu, ok);
    if (lane == 0) g_is_i64 = (m == 0xffffffffu) ? 1 : 0;
}

// ---------------------------------------------------------------------------
// Kernel 1: YZ[n, 0:256] = x[n] @ W_src ; YZ[n, 256:512] = x[n] @ W_dst
// Tiled GEMM M=20000, N=512, K=256. BM=64, BN=64, BK=16, 256 threads, 4x4 microtile.
// ---------------------------------------------------------------------------
__global__ __launch_bounds__(256) void node_gemm(const float* __restrict__ x,
                                                 const float* __restrict__ We) {
    __shared__ __align__(16) float As[16][72]; // [k][m], padded (288B rows, 16B-aligned)
    __shared__ __align__(16) float Bs[16][64]; // [k][n]

    const int m0 = blockIdx.y * 64;
    const int n0 = blockIdx.x * 64;
    const int tid = threadIdx.x;
    // cols [0,256) come from W_edge rows [0,256) (W_src); cols [256,512) from rows [256,512) (W_dst)
    const int off = (n0 >= 256) ? (256 * 256 - 256) : 0;

    const int tx = tid & 15, ty = tid >> 4;
    u64 acc[4][2] = {}; // 4 rows x 4 cols (packed pairs); bit pattern 0 == 0.0f

    for (int k0 = 0; k0 < 256; k0 += 16) {
        #pragma unroll
        for (int p = 0; p < 4; p++) {
            int idx = tid + p * 256;
            int r = idx >> 4, kk = idx & 15;
            int m = m0 + r;
            As[kk][r] = (m < NN) ? x[m * 256 + k0 + kk] : 0.f;
        }
        #pragma unroll
        for (int p = 0; p < 4; p++) {
            int idx = tid + p * 256;
            int kk = idx >> 6, n = idx & 63;
            Bs[kk][n] = We[(k0 + kk) * 256 + n0 + n + off];
        }
        __syncthreads();
        #pragma unroll
        for (int kk = 0; kk < 16; kk++) {
            float4 av = *(const float4*)&As[kk][ty * 4];
            ulonglong2 bv = *(const ulonglong2*)&Bs[kk][tx * 4];
            float a0 = av.x, a1 = av.y, a2 = av.z, a3 = av.w;
            u64 aa;
            aa = pk2(a0, a0); acc[0][0] = fma2(aa, bv.x, acc[0][0]); acc[0][1] = fma2(aa, bv.y, acc[0][1]);
            aa = pk2(a1, a1); acc[1][0] = fma2(aa, bv.x, acc[1][0]); acc[1][1] = fma2(aa, bv.y, acc[1][1]);
            aa = pk2(a2, a2); acc[2][0] = fma2(aa, bv.x, acc[2][0]); acc[2][1] = fma2(aa, bv.y, acc[2][1]);
            aa = pk2(a3, a3); acc[3][0] = fma2(aa, bv.x, acc[3][0]); acc[3][1] = fma2(aa, bv.y, acc[3][1]);
        }
        __syncthreads();
    }
    #pragma unroll
    for (int i = 0; i < 4; i++) {
        int m = m0 + ty * 4 + i;
        if (m < NN) {
            float r0, r1, r2, r3;
            upk2(acc[i][0], r0, r1);
            upk2(acc[i][1], r2, r3);
            float4 v = make_float4(r0, r1, r2, r3);
            *(float4*)&g_YZ[(size_t)m * 512 + n0 + tx * 4] = v;
        }
    }
}

// ---------------------------------------------------------------------------
// Kernel 2: zero the S accumulator (required every launch; deterministic).
// ---------------------------------------------------------------------------
__global__ void zero_s() { g_S[threadIdx.x] = 0.f; }

// ---------------------------------------------------------------------------
// Kernel 3: edge stage.
// One warp per edge iteration; lane owns 8 h-columns (32 lanes x 8 = 256).
// base = Y[src] + Z[dst] + b_edge (gather, L2-resident); for each of 4 batches:
// pre = base + attr[b,e,:16] @ W_attr (W_attr in smem, attrs via shuffle broadcast);
// acc += relu(pre). Block-level smem reduction, then global atomics.
// ---------------------------------------------------------------------------
__global__ __launch_bounds__(256) void edge_kernel(const void* __restrict__ eraw,
                                                   const float* __restrict__ attrs,
                                                   const float* __restrict__ We,
                                                   const float* __restrict__ b_edge) {
    __shared__ __align__(16) float Wsh[16 * 256]; // W_attr (rows 512..527 of W_edge)
    __shared__ float Ssh[NB * HID];

    const int tid = threadIdx.x;
    for (int i = tid; i < 16 * 256; i += 256) Wsh[i] = We[512 * 256 + i];
    for (int i = tid; i < NB * HID; i += 256) Ssh[i] = 0.f;
    __syncthreads();

    const int is64 = g_is_i64;
    const long long* e64 = (const long long*)eraw;
    const int*       e32 = (const int*)eraw;

    const int lane = tid & 31;
    const int c0 = lane * 8;
    const int gw = (blockIdx.x * 256 + tid) >> 5;
    const int nw = (gridDim.x * 256) >> 5;

    u64 bias2[4];
    #pragma unroll
    for (int j = 0; j < 4; j++) bias2[j] = pk2(b_edge[c0 + 2 * j], b_edge[c0 + 2 * j + 1]);

    // lanes 0..15 carry (b=0, a=lane) and (b=2, a=lane); lanes 16..31 carry b=1 / b=3.
    const int half = lane >> 4;
    const int ai = lane & 15;
    const float* at0 = attrs + (size_t)half * NE * 16 + ai;       // batches 0/1
    const float* at1 = attrs + (size_t)(half + 2) * NE * 16 + ai; // batches 2/3

    u64 acc[4][4] = {};

    for (int e = gw; e < NE; e += nw) {
        long long s, d;
        if (is64) { s = e64[e]; d = e64[NE + e]; }
        else      { s = e32[e]; d = e32[NE + e]; }
        const ulonglong2* yp = (const ulonglong2*)(g_YZ + (size_t)s * 512 + c0);
        const ulonglong2* zp = (const ulonglong2*)(g_YZ + (size_t)d * 512 + 256 + c0);
        ulonglong2 ya = yp[0], yb = yp[1];
        ulonglong2 za = zp[0], zb = zp[1];
        u64 base2[4];
        base2[0] = add2(add2(ya.x, za.x), bias2[0]);
        base2[1] = add2(add2(ya.y, za.y), bias2[1]);
        base2[2] = add2(add2(yb.x, zb.x), bias2[2]);
        base2[3] = add2(add2(yb.y, zb.y), bias2[3]);

        float av0 = at0[(size_t)e * 16];
        float av1 = at1[(size_t)e * 16];

        u64 pre[4][4];
        #pragma unroll
        for (int a = 0; a < 16; a++) {
            const ulonglong2* wp = (const ulonglong2*)&Wsh[a * 256 + c0];
            ulonglong2 wA = wp[0], wB = wp[1];
            u64 w2[4] = {wA.x, wA.y, wB.x, wB.y};
            float f0 = __shfl_sync(0xffffffffu, av0, a);
            float f1 = __shfl_sync(0xffffffffu, av0, 16 + a);
            float f2 = __shfl_sync(0xffffffffu, av1, a);
            float f3 = __shfl_sync(0xffffffffu, av1, 16 + a);
            u64 fb[4] = {pk2(f0, f0), pk2(f1, f1), pk2(f2, f2), pk2(f3, f3)};
            if (a == 0) {
                #pragma unroll
                for (int b = 0; b < 4; b++)
                    #pragma unroll
                    for (int j = 0; j < 4; j++)
                        pre[b][j] = fma2(fb[b], w2[j], base2[j]);
            } else {
                #pragma unroll
                for (int b = 0; b < 4; b++)
                    #pragma unroll
                    for (int j = 0; j < 4; j++)
                        pre[b][j] = fma2(fb[b], w2[j], pre[b][j]);
            }
        }
        #pragma unroll
        for (int b = 0; b < 4; b++)
            #pragma unroll
            for (int j = 0; j < 4; j++) {
                float lo, hi;
                upk2(pre[b][j], lo, hi);
                lo = fmaxf(lo, 0.f);
                hi = fmaxf(hi, 0.f);
                acc[b][j] = add2(acc[b][j], pk2(lo, hi));
            }
    }

    // per-warp accumulators -> block smem -> global
    #pragma unroll
    for (int b = 0; b < 4; b++)
        #pragma unroll
        for (int j = 0; j < 4; j++) {
            float lo, hi;
            upk2(acc[b][j], lo, hi);
            atomicAdd(&Ssh[b * 256 + c0 + 2 * j], lo);
            atomicAdd(&Ssh[b * 256 + c0 + 2 * j + 1], hi);
        }
    __syncthreads();
    for (int i = tid; i < NB * HID; i += 256) atomicAdd(&g_S[i], Ssh[i]);
}

// ---------------------------------------------------------------------------
// Kernel 4: out[b, o] = (S[b]/NE) @ W_graph + b_graph   (4 x 256 x 128, trivial)
// ---------------------------------------------------------------------------
__global__ void final_kernel(const float* __restrict__ Wg,
                             const float* __restrict__ bg,
                             float* __restrict__ out) {
    const int t = threadIdx.x; // 512 threads
    const int b = t >> 7, o = t & 127;
    const float invE = 1.0f / (float)NE;
    float dot = 0.f;
    #pragma unroll 8
    for (int h = 0; h < 256; h++)
        dot += g_S[b * 256 + h] * Wg[h * 128 + o];
    out[t] = fmaf(dot, invE, bg[o]);
}

extern "C" void kernel_launch(void* const* d_in, const int* in_sizes, int n_in,
                              void* d_out, int out_size) {
    const float* x     = (const float*)d_in[0];
    const void*  eidx  = d_in[1];
    const float* attrs = (const float*)d_in[2];
    const float* We    = (const float*)d_in[3];
    const float* be    = (const float*)d_in[4];
    const float* Wg    = (const float*)d_in[5];
    const float* bg    = (const float*)d_in[6];
    float* out = (float*)d_out;

    detect_dtype<<<1, 32>>>(eidx);
    dim3 g(8, 313); // N tiles x M tiles
    node_gemm<<<g, 256>>>(x, We);
    zero_s<<<1, NB * HID>>>();
    edge_kernel<<<592, 256>>>(eidx, attrs, We, be);
    final_kernel<<<1, 512>>>(Wg, bg, out);
}

// round 3
// speedup vs baseline: 1.3415x; 1.3415x over previous
#include <cuda_runtime.h>

#define NN 20000
#define NE 400000
#define NB 4
#define HID 256
#define OD 128

__device__ __align__(16) float g_YZ[NN * 512];
__device__ float g_S[NB * HID];
__device__ int g_is_i64;

typedef unsigned long long u64;

__device__ __forceinline__ u64 pk2(float lo, float hi) {
    u64 r;
    asm("mov.b64 %0, {%1, %2};" : "=l"(r) : "r"(__float_as_uint(lo)), "r"(__float_as_uint(hi)));
    return r;
}
__device__ __forceinline__ void upk2(u64 p, float &lo, float &hi) {
    unsigned a, b;
    asm("mov.b64 {%0, %1}, %2;" : "=r"(a), "=r"(b) : "l"(p));
    lo = __uint_as_float(a); hi = __uint_as_float(b);
}
__device__ __forceinline__ u64 fma2(u64 a, u64 b, u64 c) {
    u64 d;
    asm("fma.rn.f32x2 %0, %1, %2, %3;" : "=l"(d) : "l"(a), "l"(b), "l"(c));
    return d;
}
__device__ __forceinline__ u64 add2(u64 a, u64 b) {
    u64 d;
    asm("add.rn.f32x2 %0, %1, %2;" : "=l"(d) : "l"(a), "l"(b));
    return d;
}

// ---------------------------------------------------------------------------
// Kernel 0: dtype probe (int32 vs int64 edge_index). See R1 notes.
// ---------------------------------------------------------------------------
__global__ void detect_dtype(const void* __restrict__ eraw) {
    const long long* p = (const long long*)eraw;
    int lane = threadIdx.x;
    long long v0 = p[lane];
    long long v1 = p[64 + lane];
    bool ok = (v0 >= 0 && v0 < NN) && (v1 >= 0 && v1 < NN);
    unsigned m = __ballot_sync(0xffffffffu, ok);
    if (lane == 0) g_is_i64 = (m == 0xffffffffu) ? 1 : 0;
}

// ---------------------------------------------------------------------------
// Kernel 1: YZ = x @ [W_src | W_dst]  (unchanged from R2 — proven correct)
// ---------------------------------------------------------------------------
__global__ __launch_bounds__(256) void node_gemm(const float* __restrict__ x,
                                                 const float* __restrict__ We) {
    __shared__ __align__(16) float As[16][72];
    __shared__ __align__(16) float Bs[16][64];

    const int m0 = blockIdx.y * 64;
    const int n0 = blockIdx.x * 64;
    const int tid = threadIdx.x;
    const int off = (n0 >= 256) ? (256 * 256 - 256) : 0;

    const int tx = tid & 15, ty = tid >> 4;
    u64 acc[4][2] = {};

    for (int k0 = 0; k0 < 256; k0 += 16) {
        #pragma unroll
        for (int p = 0; p < 4; p++) {
            int idx = tid + p * 256;
            int r = idx >> 4, kk = idx & 15;
            int m = m0 + r;
            As[kk][r] = (m < NN) ? x[m * 256 + k0 + kk] : 0.f;
        }
        #pragma unroll
        for (int p = 0; p < 4; p++) {
            int idx = tid + p * 256;
            int kk = idx >> 6, n = idx & 63;
            Bs[kk][n] = We[(k0 + kk) * 256 + n0 + n + off];
        }
        __syncthreads();
        #pragma unroll
        for (int kk = 0; kk < 16; kk++) {
            float4 av = *(const float4*)&As[kk][ty * 4];
            ulonglong2 bv = *(const ulonglong2*)&Bs[kk][tx * 4];
            float a0 = av.x, a1 = av.y, a2 = av.z, a3 = av.w;
            u64 aa;
            aa = pk2(a0, a0); acc[0][0] = fma2(aa, bv.x, acc[0][0]); acc[0][1] = fma2(aa, bv.y, acc[0][1]);
            aa = pk2(a1, a1); acc[1][0] = fma2(aa, bv.x, acc[1][0]); acc[1][1] = fma2(aa, bv.y, acc[1][1]);
            aa = pk2(a2, a2); acc[2][0] = fma2(aa, bv.x, acc[2][0]); acc[2][1] = fma2(aa, bv.y, acc[2][1]);
            aa = pk2(a3, a3); acc[3][0] = fma2(aa, bv.x, acc[3][0]); acc[3][1] = fma2(aa, bv.y, acc[3][1]);
        }
        __syncthreads();
    }
    #pragma unroll
    for (int i = 0; i < 4; i++) {
        int m = m0 + ty * 4 + i;
        if (m < NN) {
            float r0, r1, r2, r3;
            upk2(acc[i][0], r0, r1);
            upk2(acc[i][1], r2, r3);
            float4 v = make_float4(r0, r1, r2, r3);
            *(float4*)&g_YZ[(size_t)m * 512 + n0 + tx * 4] = v;
        }
    }
}

__global__ void zero_s() { g_S[threadIdx.x] = 0.f; }

// ---------------------------------------------------------------------------
// Kernel 3 (v2): edge stage, W_attr slice held in REGISTERS (zero in-loop LDS).
// Lane owns 4 h-columns; warp covers 128 cols (colgroup 0/1); 2 edges per iter.
// Attr scalars broadcast via shfl (MIO pipe, overlaps fma). relu+acc fused.
// ---------------------------------------------------------------------------
__global__ __launch_bounds__(128, 3) void edge_kernel(const void* __restrict__ eraw,
                                                      const float* __restrict__ attrs,
                                                      const float* __restrict__ We,
                                                      const float* __restrict__ b_edge) {
    __shared__ float Ssh[NB * HID];
    const int tid = threadIdx.x;
    for (int i = tid; i < NB * HID; i += 128) Ssh[i] = 0.f;
    __syncthreads();

    const int lane = tid & 31;
    const int gw = (blockIdx.x * 128 + tid) >> 5;
    const int nw = (gridDim.x * 128) >> 5;     // total warps (even)
    const int colgroup = gw & 1;
    const int c0 = colgroup * 128 + lane * 4;  // 4 columns per lane
    const int p0 = gw >> 1;
    const int pstride = nw >> 1;

    // Persistent register-resident W_attr slice: 16 x 4 floats = 32 u64.
    u64 Wr0[16], Wr1[16];
    #pragma unroll
    for (int a = 0; a < 16; a++) {
        ulonglong2 w = *(const ulonglong2*)(We + 512 * 256 + a * 256 + c0);
        Wr0[a] = w.x; Wr1[a] = w.y;
    }
    const u64 biasA = pk2(b_edge[c0], b_edge[c0 + 1]);
    const u64 biasB = pk2(b_edge[c0 + 2], b_edge[c0 + 3]);

    const int is64 = g_is_i64;
    const long long* e64 = (const long long*)eraw;
    const int*       e32 = (const int*)eraw;
    const int a_l = lane & 15, eh_l = lane >> 4;

    u64 acc[4][2] = {};

    for (int p = p0; p < NE / 2; p += pstride) {
        const int e0 = 2 * p;
        long long s0, d0, s1, d1;
        if (is64) { s0 = e64[e0]; s1 = e64[e0 + 1]; d0 = e64[NE + e0]; d1 = e64[NE + e0 + 1]; }
        else      { s0 = e32[e0]; s1 = e32[e0 + 1]; d0 = e32[NE + e0]; d1 = e32[NE + e0 + 1]; }

        // attr staging: lane (eh_l, a_l) holds attr[b][e0+eh_l][a_l] for all b.
        const int ee = e0 + eh_l;
        float val0 = attrs[((size_t)0 * NE + ee) * 16 + a_l];
        float val1 = attrs[((size_t)1 * NE + ee) * 16 + a_l];
        float val2 = attrs[((size_t)2 * NE + ee) * 16 + a_l];
        float val3 = attrs[((size_t)3 * NE + ee) * 16 + a_l];

        // base = Y[src] + Z[dst] + bias (coalesced: warp covers 512B contiguous)
        ulonglong2 y0 = *(const ulonglong2*)(g_YZ + (size_t)s0 * 512 + c0);
        ulonglong2 z0 = *(const ulonglong2*)(g_YZ + (size_t)d0 * 512 + 256 + c0);
        ulonglong2 y1 = *(const ulonglong2*)(g_YZ + (size_t)s1 * 512 + c0);
        ulonglong2 z1 = *(const ulonglong2*)(g_YZ + (size_t)d1 * 512 + 256 + c0);
        u64 base00 = add2(add2(y0.x, z0.x), biasA);
        u64 base01 = add2(add2(y0.y, z0.y), biasB);
        u64 base10 = add2(add2(y1.x, z1.x), biasA);
        u64 base11 = add2(add2(y1.y, z1.y), biasB);

        #pragma unroll
        for (int eh = 0; eh < 2; eh++) {
            const u64 bA = eh ? base10 : base00;
            const u64 bB = eh ? base11 : base01;
            #pragma unroll
            for (int b = 0; b < 4; b++) {
                const float vsrc = (b == 0) ? val0 : (b == 1) ? val1 : (b == 2) ? val2 : val3;
                u64 pA = bA, pB = bB;
                #pragma unroll
                for (int a = 0; a < 16; a++) {
                    float f = __shfl_sync(0xffffffffu, vsrc, eh * 16 + a);
                    u64 fb = pk2(f, f);
                    pA = fma2(fb, Wr0[a], pA);
                    pB = fma2(fb, Wr1[a], pB);
                }
                float x0, x1, x2, x3;
                upk2(pA, x0, x1); upk2(pB, x2, x3);
                acc[b][0] = add2(acc[b][0], pk2(fmaxf(x0, 0.f), fmaxf(x1, 0.f)));
                acc[b][1] = add2(acc[b][1], pk2(fmaxf(x2, 0.f), fmaxf(x3, 0.f)));
            }
        }
    }

    // lane accumulators -> block smem -> global
    #pragma unroll
    for (int b = 0; b < 4; b++)
        #pragma unroll
        for (int j = 0; j < 2; j++) {
            float lo, hi;
            upk2(acc[b][j], lo, hi);
            atomicAdd(&Ssh[b * 256 + c0 + 2 * j], lo);
            atomicAdd(&Ssh[b * 256 + c0 + 2 * j + 1], hi);
        }
    __syncthreads();
    for (int i = tid; i < NB * HID; i += 128) atomicAdd(&g_S[i], Ssh[i]);
}

// ---------------------------------------------------------------------------
// Kernel 4: out = (S/NE) @ W_graph + b_graph
// ---------------------------------------------------------------------------
__global__ void final_kernel(const float* __restrict__ Wg,
                             const float* __restrict__ bg,
                             float* __restrict__ out) {
    const int t = threadIdx.x; // 512 threads
    const int b = t >> 7, o = t & 127;
    const float invE = 1.0f / (float)NE;
    float dot = 0.f;
    #pragma unroll 8
    for (int h = 0; h < 256; h++)
        dot += g_S[b * 256 + h] * Wg[h * 128 + o];
    out[t] = fmaf(dot, invE, bg[o]);
}

extern "C" void kernel_launch(void* const* d_in, const int* in_sizes, int n_in,
                              void* d_out, int out_size) {
    const float* x     = (const float*)d_in[0];
    const void*  eidx  = d_in[1];
    const float* attrs = (const float*)d_in[2];
    const float* We    = (const float*)d_in[3];
    const float* be    = (const float*)d_in[4];
    const float* Wg    = (const float*)d_in[5];
    const float* bg    = (const float*)d_in[6];
    float* out = (float*)d_out;

    detect_dtype<<<1, 32>>>(eidx);
    dim3 g(8, 313);
    node_gemm<<<g, 256>>>(x, We);
    zero_s<<<1, NB * HID>>>();
    edge_kernel<<<444, 128>>>(eidx, attrs, We, be);
    final_kernel<<<1, 512>>>(Wg, bg, out);
}

// round 4
// speedup vs baseline: 2.0121x; 1.4998x over previous
#include <cuda_runtime.h>

#define NN 20000
#define NE 400000
#define NB 4
#define HID 256
#define OD 128

__device__ __align__(16) float g_YZ[NN * 512];
__device__ float g_S[NB * HID];
__device__ int g_is_i64;

typedef unsigned long long u64;
typedef unsigned int u32;

__device__ __forceinline__ u64 pk2(float lo, float hi) {
    u64 r;
    asm("mov.b64 %0, {%1, %2};" : "=l"(r) : "r"(__float_as_uint(lo)), "r"(__float_as_uint(hi)));
    return r;
}
__device__ __forceinline__ void upk2(u64 p, float &lo, float &hi) {
    unsigned a, b;
    asm("mov.b64 {%0, %1}, %2;" : "=r"(a), "=r"(b) : "l"(p));
    lo = __uint_as_float(a); hi = __uint_as_float(b);
}
__device__ __forceinline__ u64 fma2(u64 a, u64 b, u64 c) {
    u64 d;
    asm("fma.rn.f32x2 %0, %1, %2, %3;" : "=l"(d) : "l"(a), "l"(b), "l"(c));
    return d;
}
__device__ __forceinline__ u64 add2(u64 a, u64 b) {
    u64 d;
    asm("add.rn.f32x2 %0, %1, %2;" : "=l"(d) : "l"(a), "l"(b));
    return d;
}
__device__ __forceinline__ u32 cvt_tf32(float f) {
    u32 r;
    asm("cvt.rna.tf32.f32 %0, %1;" : "=r"(r) : "f"(f));
    return r;
}
__device__ __forceinline__ void mma_tf32(float &d0, float &d1, float &d2, float &d3,
                                         u32 a0, u32 a1, u32 a2, u32 a3,
                                         u32 b0, u32 b1,
                                         float c0, float c1, float c2, float c3) {
    asm volatile("mma.sync.aligned.m16n8k8.row.col.f32.tf32.tf32.f32 "
                 "{%0,%1,%2,%3}, {%4,%5,%6,%7}, {%8,%9}, {%10,%11,%12,%13};"
                 : "=f"(d0), "=f"(d1), "=f"(d2), "=f"(d3)
                 : "r"(a0), "r"(a1), "r"(a2), "r"(a3), "r"(b0), "r"(b1),
                   "f"(c0), "f"(c1), "f"(c2), "f"(c3));
}

// ---------------------------------------------------------------------------
// Kernel 0: dtype probe (int32 vs int64 edge_index).
// ---------------------------------------------------------------------------
__global__ void detect_dtype(const void* __restrict__ eraw) {
    const long long* p = (const long long*)eraw;
    int lane = threadIdx.x;
    long long v0 = p[lane];
    long long v1 = p[64 + lane];
    bool ok = (v0 >= 0 && v0 < NN) && (v1 >= 0 && v1 < NN);
    unsigned m = __ballot_sync(0xffffffffu, ok);
    if (lane == 0) g_is_i64 = (m == 0xffffffffu) ? 1 : 0;
}

// ---------------------------------------------------------------------------
// Kernel 1: YZ = x @ [W_src | W_dst]  (unchanged, proven correct)
// ---------------------------------------------------------------------------
__global__ __launch_bounds__(256) void node_gemm(const float* __restrict__ x,
                                                 const float* __restrict__ We) {
    __shared__ __align__(16) float As[16][72];
    __shared__ __align__(16) float Bs[16][64];

    const int m0 = blockIdx.y * 64;
    const int n0 = blockIdx.x * 64;
    const int tid = threadIdx.x;
    const int off = (n0 >= 256) ? (256 * 256 - 256) : 0;

    const int tx = tid & 15, ty = tid >> 4;
    u64 acc[4][2] = {};

    for (int k0 = 0; k0 < 256; k0 += 16) {
        #pragma unroll
        for (int p = 0; p < 4; p++) {
            int idx = tid + p * 256;
            int r = idx >> 4, kk = idx & 15;
            int m = m0 + r;
            As[kk][r] = (m < NN) ? x[m * 256 + k0 + kk] : 0.f;
        }
        #pragma unroll
        for (int p = 0; p < 4; p++) {
            int idx = tid + p * 256;
            int kk = idx >> 6, n = idx & 63;
            Bs[kk][n] = We[(k0 + kk) * 256 + n0 + n + off];
        }
        __syncthreads();
        #pragma unroll
        for (int kk = 0; kk < 16; kk++) {
            float4 av = *(const float4*)&As[kk][ty * 4];
            ulonglong2 bv = *(const ulonglong2*)&Bs[kk][tx * 4];
            float a0 = av.x, a1 = av.y, a2 = av.z, a3 = av.w;
            u64 aa;
            aa = pk2(a0, a0); acc[0][0] = fma2(aa, bv.x, acc[0][0]); acc[0][1] = fma2(aa, bv.y, acc[0][1]);
            aa = pk2(a1, a1); acc[1][0] = fma2(aa, bv.x, acc[1][0]); acc[1][1] = fma2(aa, bv.y, acc[1][1]);
            aa = pk2(a2, a2); acc[2][0] = fma2(aa, bv.x, acc[2][0]); acc[2][1] = fma2(aa, bv.y, acc[2][1]);
            aa = pk2(a3, a3); acc[3][0] = fma2(aa, bv.x, acc[3][0]); acc[3][1] = fma2(aa, bv.y, acc[3][1]);
        }
        __syncthreads();
    }
    #pragma unroll
    for (int i = 0; i < 4; i++) {
        int m = m0 + ty * 4 + i;
        if (m < NN) {
            float r0, r1, r2, r3;
            upk2(acc[i][0], r0, r1);
            upk2(acc[i][1], r2, r3);
            float4 v = make_float4(r0, r1, r2, r3);
            *(float4*)&g_YZ[(size_t)m * 512 + n0 + tx * 4] = v;
        }
    }
}

__global__ void zero_s() { g_S[threadIdx.x] = 0.f; }

// ---------------------------------------------------------------------------
// Kernel 3 (v3): edge stage on tensor cores (mma.sync m16n8k8 tf32).
// Block = 256 thr = 8 warps; warp w owns h-col stripe [w*32, w*32+32) (4 n-tiles).
// Chunk of 32 edges: attrs (tf32-preconverted) + indices staged in smem;
// each warp runs 2 sub-iters of 16 edges (m16).
// A = attrs (from smem), B = W_attr stripe (persistent regs),
// C-init = gathered base = Y[src]+Z[dst]+bias  -> mma does broadcast-add free.
// Epilogue: relu + f32x2 accumulate per mma tile.
// ---------------------------------------------------------------------------
__global__ __launch_bounds__(256, 2) void edge_kernel(const void* __restrict__ eraw,
                                                      const float* __restrict__ attrs,
                                                      const float* __restrict__ We,
                                                      const float* __restrict__ b_edge) {
    __shared__ u32 attr_s[NB][32][20];   // [b][edge-in-chunk][attr], pad 20 (conflict-free)
    __shared__ int sidx_s[32], didx_s[32];
    __shared__ float Ssh[NB * HID];

    const int tid = threadIdx.x;
    for (int i = tid; i < NB * HID; i += 256) Ssh[i] = 0.f;

    const int warp = tid >> 5;
    const int lane = tid & 31;
    const int g = lane >> 2;      // groupID (row / edge-sub)
    const int t = lane & 3;       // threadID-in-group
    const int hbase = warp * 32;  // 32-col stripe per warp

    // Persistent B-frags: Bf[nt][kstep][reg]; b0: k=t(+8k), n=g; b1: k=t+4(+8k)
    u32 Bf[4][2][2];
    #pragma unroll
    for (int nt = 0; nt < 4; nt++)
        #pragma unroll
        for (int ks = 0; ks < 2; ks++) {
            int col = hbase + nt * 8 + g;
            Bf[nt][ks][0] = cvt_tf32(We[(512 + t + 8 * ks) * 256 + col]);
            Bf[nt][ks][1] = cvt_tf32(We[(512 + t + 4 + 8 * ks) * 256 + col]);
        }
    // Bias pairs per n-tile at h = hbase + nt*8 + 2t
    u64 bias4[4];
    #pragma unroll
    for (int nt = 0; nt < 4; nt++) {
        int h = hbase + nt * 8 + 2 * t;
        bias4[nt] = pk2(b_edge[h], b_edge[h + 1]);
    }

    const int is64 = g_is_i64;
    const long long* e64 = (const long long*)eraw;
    const int*       e32 = (const int*)eraw;

    u64 acc[NB][4] = {};  // [batch][ntile], f32x2 pairs; bitpattern 0 == 0.0f

    const int nchunks = NE / 32;
    for (int c = blockIdx.x; c < nchunks; c += gridDim.x) {
        const int e0 = c * 32;
        __syncthreads(); // previous chunk's smem reads complete
        // ---- stage indices + attrs ----
        if (tid < 32)      sidx_s[tid]      = is64 ? (int)e64[e0 + tid]           : e32[e0 + tid];
        else if (tid < 64) didx_s[tid - 32] = is64 ? (int)e64[NE + e0 + tid - 32] : e32[NE + e0 + tid - 32];
        {
            int b = tid >> 6, r = tid & 63;
            const float4* src = (const float4*)(attrs + ((size_t)b * NE + e0) * 16);
            #pragma unroll
            for (int k2 = 0; k2 < 2; k2++) {
                float4 v = src[r * 2 + k2];
                int flat = (r * 2 + k2) * 4;
                int e = flat >> 4, a = flat & 15;
                u32* dst = &attr_s[b][e][a];
                dst[0] = cvt_tf32(v.x); dst[1] = cvt_tf32(v.y);
                dst[2] = cvt_tf32(v.z); dst[3] = cvt_tf32(v.w);
            }
        }
        __syncthreads();

        #pragma unroll
        for (int sub = 0; sub < 2; sub++) {
            const int eb = sub * 16;
            const int sl = sidx_s[eb + g],     dl = didx_s[eb + g];
            const int sh = sidx_s[eb + g + 8], dh = didx_s[eb + g + 8];

            // base fragments per n-tile (C-init for mma)
            u64 bLo[4], bHi[4];
            #pragma unroll
            for (int nt = 0; nt < 4; nt++) {
                int h = hbase + nt * 8 + 2 * t;
                u64 ylo = *(const u64*)(g_YZ + (size_t)sl * 512 + h);
                u64 yhi = *(const u64*)(g_YZ + (size_t)sh * 512 + h);
                u64 zlo = *(const u64*)(g_YZ + (size_t)dl * 512 + 256 + h);
                u64 zhi = *(const u64*)(g_YZ + (size_t)dh * 512 + 256 + h);
                bLo[nt] = add2(add2(ylo, zlo), bias4[nt]);
                bHi[nt] = add2(add2(yhi, zhi), bias4[nt]);
            }

            #pragma unroll
            for (int b = 0; b < NB; b++) {
                // A frags: a0:(row g,k t) a1:(g+8,t) a2:(g,t+4) a3:(g+8,t+4); kstep1 +8
                u32 a0 = attr_s[b][eb + g][t],         a1 = attr_s[b][eb + g + 8][t];
                u32 a2 = attr_s[b][eb + g][t + 4],     a3 = attr_s[b][eb + g + 8][t + 4];
                u32 a4 = attr_s[b][eb + g][t + 8],     a5 = attr_s[b][eb + g + 8][t + 8];
                u32 a6 = attr_s[b][eb + g][t + 12],    a7 = attr_s[b][eb + g + 8][t + 12];
                #pragma unroll
                for (int nt = 0; nt < 4; nt++) {
                    float c0, c1, c2, c3;
                    upk2(bLo[nt], c0, c1);
                    upk2(bHi[nt], c2, c3);
                    float d0, d1, d2, d3;
                    mma_tf32(d0, d1, d2, d3, a0, a1, a2, a3, Bf[nt][0][0], Bf[nt][0][1], c0, c1, c2, c3);
                    mma_tf32(d0, d1, d2, d3, a4, a5, a6, a7, Bf[nt][1][0], Bf[nt][1][1], d0, d1, d2, d3);
                    acc[b][nt] = add2(acc[b][nt], pk2(fmaxf(d0, 0.f), fmaxf(d1, 0.f)));
                    acc[b][nt] = add2(acc[b][nt], pk2(fmaxf(d2, 0.f), fmaxf(d3, 0.f)));
                }
            }
        }
    }

    // ---- reduce: sum over g-groups (lanes differing in bits 2..4), t fixed ----
    #pragma unroll
    for (int b = 0; b < NB; b++)
        #pragma unroll
        for (int nt = 0; nt < 4; nt++) {
            u64 v = acc[b][nt];
            v = add2(v, __shfl_down_sync(0xffffffffu, v, 16));
            v = add2(v, __shfl_down_sync(0xffffffffu, v, 8));
            v = add2(v, __shfl_down_sync(0xffffffffu, v, 4));
            acc[b][nt] = v;
        }
    if (lane < 4) {
        #pragma unroll
        for (int b = 0; b < NB; b++)
            #pragma unroll
            for (int nt = 0; nt < 4; nt++) {
                float lo, hi;
                upk2(acc[b][nt], lo, hi);
                int h = hbase + nt * 8 + 2 * lane;
                atomicAdd(&Ssh[b * 256 + h], lo);
                atomicAdd(&Ssh[b * 256 + h + 1], hi);
            }
    }
    __syncthreads();
    for (int i = tid; i < NB * HID; i += 256) atomicAdd(&g_S[i], Ssh[i]);
}

// ---------------------------------------------------------------------------
// Kernel 4: out = (S/NE) @ W_graph + b_graph
// ---------------------------------------------------------------------------
__global__ void final_kernel(const float* __restrict__ Wg,
                             const float* __restrict__ bg,
                             float* __restrict__ out) {
    const int t = threadIdx.x; // 512 threads
    const int b = t >> 7, o = t & 127;
    const float invE = 1.0f / (float)NE;
    float dot = 0.f;
    #pragma unroll 8
    for (int h = 0; h < 256; h++)
        dot += g_S[b * 256 + h] * Wg[h * 128 + o];
    out[t] = fmaf(dot, invE, bg[o]);
}

extern "C" void kernel_launch(void* const* d_in, const int* in_sizes, int n_in,
                              void* d_out, int out_size) {
    const float* x     = (const float*)d_in[0];
    const void*  eidx  = d_in[1];
    const float* attrs = (const float*)d_in[2];
    const float* We    = (const float*)d_in[3];
    const float* be    = (const float*)d_in[4];
    const float* Wg    = (const float*)d_in[5];
    const float* bg    = (const float*)d_in[6];
    float* out = (float*)d_out;

    detect_dtype<<<1, 32>>>(eidx);
    dim3 g(8, 313);
    node_gemm<<<g, 256>>>(x, We);
    zero_s<<<1, NB * HID>>>();
    edge_kernel<<<296, 256>>>(eidx, attrs, We, be);
    final_kernel<<<1, 512>>>(Wg, bg, out);
}